// round 13
// baseline (speedup 1.0000x reference)
#include <cuda_runtime.h>

#define N_ANCHS   100800
#define NCLS      80
#define IMG_W     1280
#define IMG2      (IMG_W*IMG_W)
#define K_DETS    300
#define CAND_CAP  16384
#define SORT_N    1024
#define NBUCK     1024
#define OUTSZ     224
#define CH_ELEMS  (OUTSZ*OUTSZ)        // 50176
#define CROP_ELEMS (3*CH_ELEMS)        // 150528
#define NMS_WORDS 10                   // ceil(300/32)
#define ROWS_PER_SLAB 28
#define S_NY      34
#define S_NX      266
#define SPLIT_B   151                  // crops_A: 0..150, crops_B: 151..300

// Output layout (flattened tuple, fp32):
#define OFF_BOXES   0
#define OFF_SCORES  1200
#define OFF_CLASSES 1500
#define OFF_CROPS   1800
#define OFF_KEEP    45310728

__device__ unsigned long long g_cand[CAND_CAP];
__device__ int      g_cand_cnt;          // zero-init; re-zeroed by k_select_nms
__device__ int      g_hist[NBUCK];       // zero-init; re-zeroed by k_select_nms
__device__ unsigned char g_cls[N_ANCHS];
__device__ float4   g_fbox[K_DETS];
__device__ int      g_keep[K_DETS];

__constant__ float c_mean[3] = {0.485f, 0.456f, 0.406f};
__constant__ float c_istd[3] = {1.0f/0.229f, 1.0f/0.224f, 1.0f/0.225f};

// ---------------------------------------------------------------------------
// k_score: thread = (anchor-quad, channel-group-of-20), shfl butterflies.
__global__ void k_score(const float* __restrict__ raw) {
    int gid = blockIdx.x * blockDim.x + threadIdx.x;
    int q = gid >> 2;          // anchor quad 0..25199
    int g = gid & 3;           // channel group 0..3
    bool active = (q < N_ANCHS / 4);
    if (!active) q = 0;

    const float4* lg = (const float4*)(raw + 5 * N_ANCHS);
    const int QN = N_ANCHS / 4;

    float best[4] = {-3.4e38f, -3.4e38f, -3.4e38f, -3.4e38f};
    int   bc[4]   = {0, 0, 0, 0};
    int c0 = g * 20;
    #pragma unroll 5
    for (int c = 0; c < 20; c++) {
        float4 v = lg[(c0 + c) * QN + q];
        if (v.x > best[0]) { best[0] = v.x; bc[0] = c0 + c; }
        if (v.y > best[1]) { best[1] = v.y; bc[1] = c0 + c; }
        if (v.z > best[2]) { best[2] = v.z; bc[2] = c0 + c; }
        if (v.w > best[3]) { best[3] = v.w; bc[3] = c0 + c; }
    }
    #pragma unroll
    for (int off = 1; off <= 2; off <<= 1) {
        #pragma unroll
        for (int k = 0; k < 4; k++) {
            float ob = __shfl_xor_sync(0xffffffffu, best[k], off);
            int   oc = __shfl_xor_sync(0xffffffffu, bc[k],  off);
            if (ob > best[k] || (ob == best[k] && oc < bc[k])) {
                best[k] = ob; bc[k] = oc;
            }
        }
    }
    if (!active || g != 0) return;

    int i0 = q * 4;
    uchar4 cw = make_uchar4((unsigned char)bc[0], (unsigned char)bc[1],
                            (unsigned char)bc[2], (unsigned char)bc[3]);
    *(uchar4*)(g_cls + i0) = cw;

    #pragma unroll
    for (int k = 0; k < 4; k++) {
        int i = i0 + k;
        int cls = bc[k] + 1;
        bool allowed = (cls==1)|(cls==2)|(cls==3)|(cls==4)|(cls==6)|(cls==8)|
                       (cls==17)|(cls==18)|(cls==44);
        if (allowed && best[k] > 0.1f) {
            int b = (int)(best[k] * 170.0f);
            b = max(0, min(NBUCK - 1, b));
            atomicAdd(&g_hist[b], 1);
            int pos = atomicAdd(&g_cand_cnt, 1);
            if (pos < CAND_CAP) {
                unsigned long long key =
                    ((unsigned long long)__float_as_uint(best[k]) << 32) |
                    (unsigned long long)(0xFFFFFFFFu - (unsigned)i);
                g_cand[pos] = key;
            }
        }
    }
}

// ---------------------------------------------------------------------------
// Fused top-K selection + NMS + scalar outputs. One block, 1024 threads.
__global__ void k_select_nms(const float* __restrict__ raw, float* __restrict__ out) {
    __shared__ int sh[NBUCK];
    __shared__ int s_wsum[32], s_wexcl[32];
    __shared__ unsigned long long keys[SORT_N];
    __shared__ unsigned long long s_sorted[K_DETS];
    __shared__ float sx1[K_DETS], sy1[K_DETS], sx2[K_DETS], sy2[K_DETS], sar[K_DETS];
    __shared__ float sscore[K_DETS];
    __shared__ int   sidx[K_DETS];
    __shared__ unsigned char svalid[K_DETS];
    __shared__ unsigned s_mask[K_DETS * NMS_WORDS];
    __shared__ unsigned char s_kp[K_DETS];
    __shared__ int s_B, s_sel;
    int t = threadIdx.x;
    int lane = t & 31, wrp = t >> 5;

    // --- Phase A: suffix-sum of histogram via shfl (2 barriers) ---
    {
        int sfx = g_hist[t];
        #pragma unroll
        for (int off = 1; off < 32; off <<= 1) {
            int nv = __shfl_down_sync(0xffffffffu, sfx, off);
            if (lane + off < 32) sfx += nv;
        }
        if (lane == 0) s_wsum[wrp] = sfx;
        if (t == 0) { s_sel = 0; s_B = 0; }
        __syncthreads();
        if (t < 32) {
            int wv = s_wsum[t];
            int ws = wv;
            #pragma unroll
            for (int off = 1; off < 32; off <<= 1) {
                int nv = __shfl_down_sync(0xffffffffu, ws, off);
                if (t + off < 32) ws += nv;
            }
            s_wexcl[t] = ws - wv;     // sum over warps > t
        }
        __syncthreads();
        sh[t] = sfx + s_wexcl[wrp];   // suffix sum from bucket t
    }
    __syncthreads();

    int n_stored = min(g_cand_cnt, CAND_CAP);
    int total = sh[0];
    int target = min(K_DETS, min(total, n_stored));
    if (target > 0) {
        if (sh[t] >= target && (t == NBUCK - 1 || sh[t + 1] < target)) s_B = t;
    }
    keys[t] = 0ull;
    __syncthreads();
    int B = s_B;

    // --- Phase B: gather survivors ---
    if (target > 0) {
        for (int i = t; i < n_stored; i += blockDim.x) {
            unsigned long long key = g_cand[i];
            float s = __uint_as_float((unsigned)(key >> 32));
            int b = (int)(s * 170.0f);
            b = max(0, min(NBUCK - 1, b));
            if (b >= B) {
                int p = atomicAdd(&s_sel, 1);
                if (p < SORT_N) keys[p] = key;
            }
        }
    }
    __syncthreads();

    // --- Phase C: rank-based selection (keys unique -> ranks distinct) ---
    {
        int n = min(s_sel, SORT_N);
        if (t < n) {
            unsigned long long mykey = keys[t];
            int rank = 0;
            for (int i = 0; i < n; i++)
                rank += (keys[i] > mykey) ? 1 : 0;
            if (rank < K_DETS) s_sorted[rank] = mykey;
        }
    }
    __syncthreads();

    // --- Phase D: decode top-300 boxes into smem; re-zero persistent state ---
    if (t < K_DETS) {
        int idx = -1;
        float sc = 0.0f;
        if (t < target) {
            unsigned long long key = s_sorted[t];
            idx = (int)(0xFFFFFFFFu - (unsigned)(key & 0xFFFFFFFFull));
            sc  = __uint_as_float((unsigned)(key >> 32));
        }
        sidx[t]   = idx;
        sscore[t] = sc;
        float x1 = 0.f, y1 = 0.f, x2 = 0.f, y2 = 0.f;
        if (idx >= 0) {
            float cx = raw[idx];
            float cy = raw[N_ANCHS + idx];
            float w  = raw[2 * N_ANCHS + idx];
            float h  = raw[3 * N_ANCHS + idx];
            x1 = cx - w * 0.5f; y1 = cy - h * 0.5f;
            x2 = cx + w * 0.5f; y2 = cy + h * 0.5f;
        }
        sx1[t] = x1; sy1[t] = y1; sx2[t] = x2; sy2[t] = y2;
        sar[t] = (x2 - x1) * (y2 - y1);
        svalid[t] = (idx >= 0) ? 1 : 0;
    }
    g_hist[t] = 0;
    if (t == 0) g_cand_cnt = 0;
    __syncthreads();

    // --- Phase E: mask build (div-free IOU: inter/uni>thr <=> inter>thr*uni,
    // uni>0; degenerate zero-area rows give inter=uni=0 -> false as in ref) ---
    {
        for (int i = wrp; i < K_DETS; i += 32) {
            float ix1 = sx1[i], iy1 = sy1[i], ix2 = sx2[i], iy2 = sy2[i], ia = sar[i];
            #pragma unroll
            for (int w = 0; w < NMS_WORDS; w++) {
                int j = (w << 5) + lane;
                bool sup = false;
                if (j < K_DETS && j > i) {
                    float lx = fmaxf(ix1, sx1[j]);
                    float ly = fmaxf(iy1, sy1[j]);
                    float rx = fminf(ix2, sx2[j]);
                    float ry = fminf(iy2, sy2[j]);
                    float iw = fmaxf(rx - lx, 0.0f);
                    float ih = fmaxf(ry - ly, 0.0f);
                    float inter = iw * ih;
                    float uni = ia + sar[j] - inter;
                    sup = inter > 0.45f * uni;
                }
                unsigned m = __ballot_sync(0xffffffffu, sup);
                if (lane == 0) s_mask[i * NMS_WORDS + w] = m;
            }
        }
    }
    __syncthreads();

    // --- Phase F: greedy scan, warp 0; lane w owns removal word w ---
    if (t < 32) {
        unsigned rm = 0;
        #pragma unroll
        for (int w = 0; w < NMS_WORDS; w++) {
            int j = (w << 5) + t;
            bool inv = (j < K_DETS) ? (svalid[j] == 0) : false;
            unsigned bword = __ballot_sync(0xffffffffu, inv);
            if (t == w) rm = bword;
        }
        unsigned cur = (t < NMS_WORDS) ? s_mask[t] : 0;
        for (int i = 0; i < K_DETS; i++) {
            unsigned nxt = (t < NMS_WORDS && i + 1 < K_DETS)
                           ? s_mask[(i + 1) * NMS_WORDS + t] : 0;
            unsigned word = __shfl_sync(0xffffffffu, rm, i >> 5);
            bool alive = !((word >> (i & 31)) & 1u);
            if (alive) rm |= cur;
            if (t == 0) s_kp[i] = alive ? 1 : 0;
            cur = nxt;
        }
    }
    __syncthreads();

    // --- Phase G: scalar outputs ---
    if (t < K_DETS) {
        int k = s_kp[t];
        float fx1 = k ? sx1[t] : 0.f, fy1 = k ? sy1[t] : 0.f;
        float fx2 = k ? sx2[t] : 0.f, fy2 = k ? sy2[t] : 0.f;
        out[OFF_BOXES + 4 * t + 0] = fx1;
        out[OFF_BOXES + 4 * t + 1] = fy1;
        out[OFF_BOXES + 4 * t + 2] = fx2;
        out[OFF_BOXES + 4 * t + 3] = fy2;
        out[OFF_SCORES + t] = k ? sscore[t] : 0.0f;
        int cv = 0;
        int idx = sidx[t];
        if (k && idx >= 0) cv = (int)g_cls[idx] + 1;
        out[OFF_CLASSES + t] = (float)cv;
        out[OFF_KEEP + t]    = k ? 1.0f : 0.0f;
        g_fbox[t] = make_float4(fx1, fy1, fx2, fy2);
        g_keep[t] = k;
    }
}

// ---------------------------------------------------------------------------
// Crops: b_base + blockIdx.y selects the crop. b==0 -> full-image resize;
// b>0 -> ROI: smem-staged window + smem y-table + register row-pair cache.
__global__ void __launch_bounds__(224) k_crops(const float* __restrict__ img,
                                               float* __restrict__ out,
                                               int b_base) {
    __shared__ float s_img[S_NY * S_NX];
    __shared__ float4 s_yt[ROWS_PER_SLAB];
    int t = threadIdx.x;                // xo 0..223
    int b = b_base + blockIdx.y;        // 0..300
    int c = blockIdx.x >> 3;            // 0..2
    int slab = blockIdx.x & 7;          // 0..7
    int r0 = slab * ROWS_PER_SLAB;

    float istd = c_istd[c];
    float nmean = -c_mean[c] * istd;
    float* dst = out + OFF_CROPS + (size_t)b * CROP_ELEMS + c * CH_ELEMS
                 + r0 * OUTSZ + t;
    const float* base = img + c * IMG2;
    const float inv = 1.0f / (float)OUTSZ;

    if (b == 0) {
        float xs = ((float)t + 0.5f) * inv * (float)IMG_W - 0.5f;
        float xc = fminf(fmaxf(xs, 0.0f), (float)(IMG_W - 1));
        int x0 = (int)floorf(xc);
        int x1i = min(x0 + 1, IMG_W - 1);
        float lx = xc - (float)x0;
        #pragma unroll 4
        for (int row = 0; row < ROWS_PER_SLAB; row++) {
            float ys = ((float)(r0 + row) + 0.5f) * inv * (float)IMG_W - 0.5f;
            float yc = fminf(fmaxf(ys, 0.0f), (float)(IMG_W - 1));
            int y0 = (int)floorf(yc);
            int y1 = min(y0 + 1, IMG_W - 1);
            float ly = yc - (float)y0;
            const float* p0 = base + y0 * IMG_W;
            const float* p1 = base + y1 * IMG_W;
            float v00 = p0[x0], v01 = p0[x1i], v10 = p1[x0], v11 = p1[x1i];
            float top = fmaf(v01 - v00, lx, v00);
            float bot = fmaf(v11 - v10, lx, v10);
            float val = fmaf(bot - top, ly, top);
            dst[row * OUTSZ] = fmaf(val, istd, nmean);
        }
        return;
    }

    int kpF = g_keep[b - 1];
    if (!kpF) {
        #pragma unroll 4
        for (int row = 0; row < ROWS_PER_SLAB; row++) dst[row * OUTSZ] = nmean;
        return;
    }
    float4 bb = g_fbox[b - 1];
    float w = bb.z - bb.x, h = bb.w - bb.y;

    float xsA = bb.x - 0.5f + (0.5f   * inv) * w;
    float xsB = bb.x - 0.5f + (223.5f * inv) * w;
    int X0 = (int)floorf(fminf(fmaxf(xsA, 0.0f), (float)(IMG_W - 1)));
    int Xe = (int)floorf(fminf(fmaxf(xsB, 0.0f), (float)(IMG_W - 1)));
    int NX = min(Xe + 1, IMG_W - 1) - X0 + 1;
    NX = min(NX, S_NX);
    float ysA = bb.y - 0.5f + (((float)r0 + 0.5f)  * inv) * h;
    float ysB = bb.y - 0.5f + (((float)r0 + 27.5f) * inv) * h;
    int Y0 = (int)floorf(fminf(fmaxf(ysA, 0.0f), (float)(IMG_W - 1)));
    int Ye = (int)floorf(fminf(fmaxf(ysB, 0.0f), (float)(IMG_W - 1)));
    int NY = min(Ye + 1, IMG_W - 1) - Y0 + 1;
    NY = min(NY, S_NY);

    // y-table: (ly, yr*NX, yr1*NX, vy) for the 28 output rows of this slab.
    if (t < ROWS_PER_SLAB) {
        float ys = bb.y - 0.5f + (((float)(r0 + t) + 0.5f) * inv) * h;
        float vy = (ys >= -1.0f && ys <= (float)IMG_W) ? 1.0f : 0.0f;
        float yc = fminf(fmaxf(ys, 0.0f), (float)(IMG_W - 1));
        float y0f = floorf(yc);
        int yr = (int)y0f - Y0;
        int yr1 = min(yr + 1, NY - 1);
        s_yt[t] = make_float4(yc - y0f, (float)(yr * NX), (float)(yr1 * NX), vy);
    }

    // Stage source window (coalesced rows, magic-division row split).
    {
        int tot = NY * NX;
        unsigned magic = 0xFFFFFFFFu / (unsigned)NX + 1u;
        const float* src = base + Y0 * IMG_W + X0;
        for (int i = t; i < tot; i += 224) {
            int row = (int)__umulhi((unsigned)i, magic);
            int col = i - row * NX;
            s_img[i] = src[row * IMG_W + col];
        }
    }
    __syncthreads();

    float xs = bb.x - 0.5f + (((float)t + 0.5f) * inv) * w;
    float vx = (xs >= -1.0f && xs <= (float)IMG_W) ? 1.0f : 0.0f;
    float xc = fminf(fmaxf(xs, 0.0f), (float)(IMG_W - 1));
    float x0f = floorf(xc);
    float lx = xc - x0f;
    int xr = (int)x0f - X0;
    int xr1 = min(xr + 1, NX - 1);

    float t00 = 0.f, t01 = 0.f, b00 = 0.f, b01 = 0.f;
    int prevYo = -1000, prevYo1 = -1000;

    for (int row = 0; row < ROWS_PER_SLAB; row++) {
        float4 yt = s_yt[row];           // broadcast LDS.128
        int yo  = (int)yt.y;             // yr*NX
        int yo1 = (int)yt.z;             // yr1*NX
        float ly = yt.x;

        if (yo != prevYo) {              // warp-uniform
            if (yo == prevYo1) { t00 = b00; t01 = b01; }
            else {
                t00 = s_img[yo + xr];
                t01 = s_img[yo + xr1];
            }
        }
        if (yo1 != prevYo1) {            // warp-uniform
            if (yo1 == yo) { b00 = t00; b01 = t01; }
            else {
                b00 = s_img[yo1 + xr];
                b01 = s_img[yo1 + xr1];
            }
        }
        prevYo = yo; prevYo1 = yo1;

        float top = fmaf(t01 - t00, lx, t00);
        float bot = fmaf(b01 - b00, lx, b00);
        float val = fmaf(bot - top, ly, top) * (vx * yt.w);
        dst[row * OUTSZ] = fmaf(val, istd, nmean);
    }
}

// ---------------------------------------------------------------------------
extern "C" void kernel_launch(void* const* d_in, const int* in_sizes, int n_in,
                              void* d_out, int out_size) {
    const float* raw = (const float*)d_in[0];   // (1,85,100800)
    const float* img = (const float*)d_in[1];   // (1,3,1280,1280)
    float* out = (float*)d_out;

    k_score<<<(N_ANCHS + 255) / 256, 256>>>(raw);
    k_select_nms<<<1, 1024>>>(raw, out);
    dim3 gA(24, SPLIT_B);                       // crops 0..150
    k_crops<<<gA, 224>>>(img, out, 0);
    dim3 gB(24, 301 - SPLIT_B);                 // crops 151..300 (profiled: idx 3)
    k_crops<<<gB, 224>>>(img, out, SPLIT_B);
}

// round 14
// speedup vs baseline: 1.1192x; 1.1192x over previous
#include <cuda_runtime.h>

#define N_ANCHS   100800
#define NCLS      80
#define IMG_W     1280
#define IMG2      (IMG_W*IMG_W)
#define IMG_W4    (IMG_W/4)
#define K_DETS    300
#define CAND_CAP  16384
#define SORT_N    1024
#define NBUCK     1024
#define OUTSZ     224
#define CH_ELEMS  (OUTSZ*OUTSZ)        // 50176
#define CROP_ELEMS (3*CH_ELEMS)        // 150528
#define NMS_WORDS 10                   // ceil(300/32)
#define ROWS_PER_SLAB 28
#define SLAB_PX   (ROWS_PER_SLAB*OUTSZ)  // 6272
#define S_NY      34
#define S_NXS     272                  // padded smem row stride (mult of 4)

// Output layout (flattened tuple, fp32):
#define OFF_BOXES   0
#define OFF_SCORES  1200
#define OFF_CLASSES 1500
#define OFF_CROPS   1800
#define OFF_KEEP    45310728

__device__ unsigned long long g_cand[CAND_CAP];
__device__ int      g_cand_cnt;          // zero-init; re-zeroed by k_select_nms
__device__ int      g_hist[NBUCK];       // zero-init; re-zeroed by k_select_nms
__device__ unsigned char g_cls[N_ANCHS];
__device__ float4   g_fbox[K_DETS];
__device__ int      g_keep[K_DETS];

__constant__ float c_mean[3] = {0.485f, 0.456f, 0.406f};
__constant__ float c_istd[3] = {1.0f/0.229f, 1.0f/0.224f, 1.0f/0.225f};

// ---------------------------------------------------------------------------
// k_score: thread = (anchor-quad, channel-group-of-20), shfl butterflies.
__global__ void k_score(const float* __restrict__ raw) {
    int gid = blockIdx.x * blockDim.x + threadIdx.x;
    int q = gid >> 2;          // anchor quad 0..25199
    int g = gid & 3;           // channel group 0..3
    bool active = (q < N_ANCHS / 4);
    if (!active) q = 0;

    const float4* lg = (const float4*)(raw + 5 * N_ANCHS);
    const int QN = N_ANCHS / 4;

    float best[4] = {-3.4e38f, -3.4e38f, -3.4e38f, -3.4e38f};
    int   bc[4]   = {0, 0, 0, 0};
    int c0 = g * 20;
    #pragma unroll 5
    for (int c = 0; c < 20; c++) {
        float4 v = lg[(c0 + c) * QN + q];
        if (v.x > best[0]) { best[0] = v.x; bc[0] = c0 + c; }
        if (v.y > best[1]) { best[1] = v.y; bc[1] = c0 + c; }
        if (v.z > best[2]) { best[2] = v.z; bc[2] = c0 + c; }
        if (v.w > best[3]) { best[3] = v.w; bc[3] = c0 + c; }
    }
    #pragma unroll
    for (int off = 1; off <= 2; off <<= 1) {
        #pragma unroll
        for (int k = 0; k < 4; k++) {
            float ob = __shfl_xor_sync(0xffffffffu, best[k], off);
            int   oc = __shfl_xor_sync(0xffffffffu, bc[k],  off);
            if (ob > best[k] || (ob == best[k] && oc < bc[k])) {
                best[k] = ob; bc[k] = oc;
            }
        }
    }
    if (!active || g != 0) return;

    int i0 = q * 4;
    uchar4 cw = make_uchar4((unsigned char)bc[0], (unsigned char)bc[1],
                            (unsigned char)bc[2], (unsigned char)bc[3]);
    *(uchar4*)(g_cls + i0) = cw;

    #pragma unroll
    for (int k = 0; k < 4; k++) {
        int i = i0 + k;
        int cls = bc[k] + 1;
        bool allowed = (cls==1)|(cls==2)|(cls==3)|(cls==4)|(cls==6)|(cls==8)|
                       (cls==17)|(cls==18)|(cls==44);
        if (allowed && best[k] > 0.1f) {
            int b = (int)(best[k] * 170.0f);
            b = max(0, min(NBUCK - 1, b));
            atomicAdd(&g_hist[b], 1);
            int pos = atomicAdd(&g_cand_cnt, 1);
            if (pos < CAND_CAP) {
                unsigned long long key =
                    ((unsigned long long)__float_as_uint(best[k]) << 32) |
                    (unsigned long long)(0xFFFFFFFFu - (unsigned)i);
                g_cand[pos] = key;
            }
        }
    }
}

// ---------------------------------------------------------------------------
// Fused top-K selection + NMS + scalar outputs. One block, 1024 threads.
__global__ void k_select_nms(const float* __restrict__ raw, float* __restrict__ out) {
    __shared__ int sh[NBUCK];
    __shared__ int s_wsum[32], s_wexcl[32];
    __shared__ unsigned long long keys[SORT_N];
    __shared__ unsigned long long s_sorted[K_DETS];
    __shared__ float sx1[K_DETS], sy1[K_DETS], sx2[K_DETS], sy2[K_DETS], sar[K_DETS];
    __shared__ float sscore[K_DETS];
    __shared__ int   sidx[K_DETS];
    __shared__ unsigned char svalid[K_DETS];
    __shared__ unsigned s_mask[K_DETS * NMS_WORDS];
    __shared__ unsigned char s_kp[K_DETS];
    __shared__ int s_B, s_sel;
    int t = threadIdx.x;
    int lane = t & 31, wrp = t >> 5;

    // --- Phase A: suffix-sum of histogram via shfl (2 barriers) ---
    {
        int sfx = g_hist[t];
        #pragma unroll
        for (int off = 1; off < 32; off <<= 1) {
            int nv = __shfl_down_sync(0xffffffffu, sfx, off);
            if (lane + off < 32) sfx += nv;
        }
        if (lane == 0) s_wsum[wrp] = sfx;
        if (t == 0) { s_sel = 0; s_B = 0; }
        __syncthreads();
        if (t < 32) {
            int wv = s_wsum[t];
            int ws = wv;
            #pragma unroll
            for (int off = 1; off < 32; off <<= 1) {
                int nv = __shfl_down_sync(0xffffffffu, ws, off);
                if (t + off < 32) ws += nv;
            }
            s_wexcl[t] = ws - wv;     // sum over warps > t
        }
        __syncthreads();
        sh[t] = sfx + s_wexcl[wrp];   // suffix sum from bucket t
    }
    __syncthreads();

    int n_stored = min(g_cand_cnt, CAND_CAP);
    int total = sh[0];
    int target = min(K_DETS, min(total, n_stored));
    if (target > 0) {
        if (sh[t] >= target && (t == NBUCK - 1 || sh[t + 1] < target)) s_B = t;
    }
    keys[t] = 0ull;
    __syncthreads();
    int B = s_B;

    // --- Phase B: gather survivors ---
    if (target > 0) {
        for (int i = t; i < n_stored; i += blockDim.x) {
            unsigned long long key = g_cand[i];
            float s = __uint_as_float((unsigned)(key >> 32));
            int b = (int)(s * 170.0f);
            b = max(0, min(NBUCK - 1, b));
            if (b >= B) {
                int p = atomicAdd(&s_sel, 1);
                if (p < SORT_N) keys[p] = key;
            }
        }
    }
    __syncthreads();

    // --- Phase C: rank-based selection (keys unique -> ranks distinct) ---
    {
        int n = min(s_sel, SORT_N);
        if (t < n) {
            unsigned long long mykey = keys[t];
            int rank = 0;
            for (int i = 0; i < n; i++)
                rank += (keys[i] > mykey) ? 1 : 0;
            if (rank < K_DETS) s_sorted[rank] = mykey;
        }
    }
    __syncthreads();

    // --- Phase D: decode top-300 boxes into smem; re-zero persistent state ---
    if (t < K_DETS) {
        int idx = -1;
        float sc = 0.0f;
        if (t < target) {
            unsigned long long key = s_sorted[t];
            idx = (int)(0xFFFFFFFFu - (unsigned)(key & 0xFFFFFFFFull));
            sc  = __uint_as_float((unsigned)(key >> 32));
        }
        sidx[t]   = idx;
        sscore[t] = sc;
        float x1 = 0.f, y1 = 0.f, x2 = 0.f, y2 = 0.f;
        if (idx >= 0) {
            float cx = raw[idx];
            float cy = raw[N_ANCHS + idx];
            float w  = raw[2 * N_ANCHS + idx];
            float h  = raw[3 * N_ANCHS + idx];
            x1 = cx - w * 0.5f; y1 = cy - h * 0.5f;
            x2 = cx + w * 0.5f; y2 = cy + h * 0.5f;
        }
        sx1[t] = x1; sy1[t] = y1; sx2[t] = x2; sy2[t] = y2;
        sar[t] = (x2 - x1) * (y2 - y1);
        svalid[t] = (idx >= 0) ? 1 : 0;
    }
    g_hist[t] = 0;
    if (t == 0) g_cand_cnt = 0;
    __syncthreads();

    // --- Phase E: mask build (div-free IOU: inter/uni>thr <=> inter>thr*uni,
    // uni>0; degenerate zero-area rows give inter=uni=0 -> false as in ref) ---
    {
        for (int i = wrp; i < K_DETS; i += 32) {
            float ix1 = sx1[i], iy1 = sy1[i], ix2 = sx2[i], iy2 = sy2[i], ia = sar[i];
            #pragma unroll
            for (int w = 0; w < NMS_WORDS; w++) {
                int j = (w << 5) + lane;
                bool sup = false;
                if (j < K_DETS && j > i) {
                    float lx = fmaxf(ix1, sx1[j]);
                    float ly = fmaxf(iy1, sy1[j]);
                    float rx = fminf(ix2, sx2[j]);
                    float ry = fminf(iy2, sy2[j]);
                    float iw = fmaxf(rx - lx, 0.0f);
                    float ih = fmaxf(ry - ly, 0.0f);
                    float inter = iw * ih;
                    float uni = ia + sar[j] - inter;
                    sup = inter > 0.45f * uni;
                }
                unsigned m = __ballot_sync(0xffffffffu, sup);
                if (lane == 0) s_mask[i * NMS_WORDS + w] = m;
            }
        }
    }
    __syncthreads();

    // --- Phase F: greedy scan, warp 0; lane w owns removal word w ---
    if (t < 32) {
        unsigned rm = 0;
        #pragma unroll
        for (int w = 0; w < NMS_WORDS; w++) {
            int j = (w << 5) + t;
            bool inv = (j < K_DETS) ? (svalid[j] == 0) : false;
            unsigned bword = __ballot_sync(0xffffffffu, inv);
            if (t == w) rm = bword;
        }
        unsigned cur = (t < NMS_WORDS) ? s_mask[t] : 0;
        for (int i = 0; i < K_DETS; i++) {
            unsigned nxt = (t < NMS_WORDS && i + 1 < K_DETS)
                           ? s_mask[(i + 1) * NMS_WORDS + t] : 0;
            unsigned word = __shfl_sync(0xffffffffu, rm, i >> 5);
            bool alive = !((word >> (i & 31)) & 1u);
            if (alive) rm |= cur;
            if (t == 0) s_kp[i] = alive ? 1 : 0;
            cur = nxt;
        }
    }
    __syncthreads();

    // --- Phase G: scalar outputs ---
    if (t < K_DETS) {
        int k = s_kp[t];
        float fx1 = k ? sx1[t] : 0.f, fy1 = k ? sy1[t] : 0.f;
        float fx2 = k ? sx2[t] : 0.f, fy2 = k ? sy2[t] : 0.f;
        out[OFF_BOXES + 4 * t + 0] = fx1;
        out[OFF_BOXES + 4 * t + 1] = fy1;
        out[OFF_BOXES + 4 * t + 2] = fx2;
        out[OFF_BOXES + 4 * t + 3] = fy2;
        out[OFF_SCORES + t] = k ? sscore[t] : 0.0f;
        int cv = 0;
        int idx = sidx[t];
        if (k && idx >= 0) cv = (int)g_cls[idx] + 1;
        out[OFF_CLASSES + t] = (float)cv;
        out[OFF_KEEP + t]    = k ? 1.0f : 0.0f;
        g_fbox[t] = make_float4(fx1, fy1, fx2, fy2);
        g_keep[t] = k;
    }
}

// ---------------------------------------------------------------------------
// Crops: grid (24, 301). b==0 -> full-image resize. b>0 -> ROI with
// float4-staged smem window (16B-aligned), bitcast y-table, register row cache.
__global__ void __launch_bounds__(224) k_crops(const float* __restrict__ img,
                                               float* __restrict__ out) {
    __shared__ float s_img[S_NY * S_NXS];
    __shared__ float4 s_yt[ROWS_PER_SLAB];
    int t = threadIdx.x;                // xo 0..223
    int b = blockIdx.y;                 // 0..300
    int c = blockIdx.x >> 3;            // 0..2
    int slab = blockIdx.x & 7;          // 0..7
    int r0 = slab * ROWS_PER_SLAB;

    float istd = c_istd[c];
    float nmean = -c_mean[c] * istd;
    float* dst = out + OFF_CROPS + (size_t)b * CROP_ELEMS + c * CH_ELEMS
                 + r0 * OUTSZ + t;
    const float* base = img + c * IMG2;
    const float inv = 1.0f / (float)OUTSZ;

    if (b == 0) {
        float xs = ((float)t + 0.5f) * inv * (float)IMG_W - 0.5f;
        float xc = fminf(fmaxf(xs, 0.0f), (float)(IMG_W - 1));
        int x0 = (int)floorf(xc);
        int x1i = min(x0 + 1, IMG_W - 1);
        float lx = xc - (float)x0;
        #pragma unroll 4
        for (int row = 0; row < ROWS_PER_SLAB; row++) {
            float ys = ((float)(r0 + row) + 0.5f) * inv * (float)IMG_W - 0.5f;
            float yc = fminf(fmaxf(ys, 0.0f), (float)(IMG_W - 1));
            int y0 = (int)floorf(yc);
            int y1 = min(y0 + 1, IMG_W - 1);
            float ly = yc - (float)y0;
            const float* p0 = base + y0 * IMG_W;
            const float* p1 = base + y1 * IMG_W;
            float v00 = p0[x0], v01 = p0[x1i], v10 = p1[x0], v11 = p1[x1i];
            float top = fmaf(v01 - v00, lx, v00);
            float bot = fmaf(v11 - v10, lx, v10);
            float val = fmaf(bot - top, ly, top);
            dst[row * OUTSZ] = fmaf(val, istd, nmean);
        }
        return;
    }

    int kpF = g_keep[b - 1];
    if (!kpF) {
        // float4 fill of the whole slab (aligned: all offsets mult of 4)
        float z = nmean;
        float4 z4 = make_float4(z, z, z, z);
        float4* d4 = (float4*)(out + OFF_CROPS + (size_t)b * CROP_ELEMS
                               + c * CH_ELEMS + r0 * OUTSZ);
        #pragma unroll
        for (int i = 0; i < SLAB_PX / 4 / 224; i++)
            d4[i * 224 + t] = z4;
        return;
    }
    float4 bb = g_fbox[b - 1];
    float w = bb.z - bb.x, h = bb.w - bb.y;

    // Source-window bounds (uniform per block).
    float xsA = bb.x - 0.5f + (0.5f   * inv) * w;
    float xsB = bb.x - 0.5f + (223.5f * inv) * w;
    int X0 = (int)floorf(fminf(fmaxf(xsA, 0.0f), (float)(IMG_W - 1)));
    int Xe = (int)floorf(fminf(fmaxf(xsB, 0.0f), (float)(IMG_W - 1)));
    int X0a = X0 & ~3;                          // 16B-aligned start
    int XHI = min(Xe + 1, IMG_W - 1);
    int NXa = XHI - X0a + 1;                    // valid staged width
    int NXs = (NXa + 3) & ~3;                   // padded smem stride
    NXs = min(NXs, S_NXS);
    float ysA = bb.y - 0.5f + (((float)r0 + 0.5f)  * inv) * h;
    float ysB = bb.y - 0.5f + (((float)r0 + 27.5f) * inv) * h;
    int Y0 = (int)floorf(fminf(fmaxf(ysA, 0.0f), (float)(IMG_W - 1)));
    int Ye = (int)floorf(fminf(fmaxf(ysB, 0.0f), (float)(IMG_W - 1)));
    int NY = min(Ye + 1, IMG_W - 1) - Y0 + 1;
    NY = min(NY, S_NY);

    // y-table: (ly, bitcast(yr*NXs), bitcast(yr1*NXs), vy).
    if (t < ROWS_PER_SLAB) {
        float ys = bb.y - 0.5f + (((float)(r0 + t) + 0.5f) * inv) * h;
        float vy = (ys >= -1.0f && ys <= (float)IMG_W) ? 1.0f : 0.0f;
        float yc = fminf(fmaxf(ys, 0.0f), (float)(IMG_W - 1));
        float y0f = floorf(yc);
        int yr = (int)y0f - Y0;
        int yr1 = min(yr + 1, NY - 1);
        s_yt[t] = make_float4(yc - y0f, __int_as_float(yr * NXs),
                              __int_as_float(yr1 * NXs), vy);
    }

    // float4 staging: rows are 16B-aligned from base+Y0*IMG_W+X0a.
    {
        int n4 = NXs >> 2;
        int tot4 = NY * n4;
        unsigned magic = 0xFFFFFFFFu / (unsigned)n4 + 1u;
        const float4* src4 = (const float4*)(base + Y0 * IMG_W + X0a);
        int limit4 = (IMG2 - (Y0 * IMG_W + X0a)) / 4 - 1;  // stay inside image
        float4* s4 = (float4*)s_img;
        for (int i = t; i < tot4; i += 224) {
            int row = (int)__umulhi((unsigned)i, magic);
            int col = i - row * n4;
            int off = min(row * IMG_W4 + col, limit4);     // clamped lanes land
            s4[row * n4 + col] = src4[off];                // only in padding
        }
    }
    __syncthreads();

    float xs = bb.x - 0.5f + (((float)t + 0.5f) * inv) * w;
    float vx = (xs >= -1.0f && xs <= (float)IMG_W) ? 1.0f : 0.0f;
    float xc = fminf(fmaxf(xs, 0.0f), (float)(IMG_W - 1));
    float x0f = floorf(xc);
    float lx = xc - x0f;
    int xr = (int)x0f - X0a;
    int xr1 = min(xr + 1, NXa - 1);

    float t00 = 0.f, t01 = 0.f, b00 = 0.f, b01 = 0.f;
    int prevYo = -1000, prevYo1 = -1000;

    #pragma unroll 4
    for (int row = 0; row < ROWS_PER_SLAB; row++) {
        float4 yt = s_yt[row];           // broadcast LDS.128
        int yo  = __float_as_int(yt.y);  // yr*NXs (bitcast, no F2I)
        int yo1 = __float_as_int(yt.z);  // yr1*NXs
        float ly = yt.x;

        if (yo != prevYo) {              // warp-uniform
            if (yo == prevYo1) { t00 = b00; t01 = b01; }
            else {
                t00 = s_img[yo + xr];
                t01 = s_img[yo + xr1];
            }
        }
        if (yo1 != prevYo1) {            // warp-uniform
            if (yo1 == yo) { b00 = t00; b01 = t01; }
            else {
                b00 = s_img[yo1 + xr];
                b01 = s_img[yo1 + xr1];
            }
        }
        prevYo = yo; prevYo1 = yo1;

        float top = fmaf(t01 - t00, lx, t00);
        float bot = fmaf(b01 - b00, lx, b00);
        float val = fmaf(bot - top, ly, top) * (vx * yt.w);
        dst[row * OUTSZ] = fmaf(val, istd, nmean);
    }
}

// ---------------------------------------------------------------------------
extern "C" void kernel_launch(void* const* d_in, const int* in_sizes, int n_in,
                              void* d_out, int out_size) {
    const float* raw = (const float*)d_in[0];   // (1,85,100800)
    const float* img = (const float*)d_in[1];   // (1,3,1280,1280)
    float* out = (float*)d_out;

    k_score<<<(N_ANCHS + 255) / 256, 256>>>(raw);
    k_select_nms<<<1, 1024>>>(raw, out);
    dim3 g(24, 301);                            // (3 ch x 8 slabs, 301 crops)
    k_crops<<<g, 224>>>(img, out);
}

// round 15
// speedup vs baseline: 1.1432x; 1.0215x over previous
#include <cuda_runtime.h>

#define N_ANCHS   100800
#define NCLS      80
#define IMG_W     1280
#define IMG2      (IMG_W*IMG_W)
#define IMG_W4    (IMG_W/4)
#define K_DETS    300
#define CAND_CAP  16384
#define SORT_N    1024
#define NBUCK     1024
#define OUTSZ     224
#define CH_ELEMS  (OUTSZ*OUTSZ)        // 50176
#define CROP_ELEMS (3*CH_ELEMS)        // 150528
#define NMS_WORDS 10                   // ceil(300/32)
#define ROWS_PER_SLAB 28
#define SLAB_PX   (ROWS_PER_SLAB*OUTSZ)  // 6272
#define S_NY      34
#define S_NXS     272                  // padded smem row stride (mult of 4)

// Output layout (flattened tuple, fp32):
#define OFF_BOXES   0
#define OFF_SCORES  1200
#define OFF_CLASSES 1500
#define OFF_CROPS   1800
#define OFF_KEEP    45310728

__device__ unsigned long long g_cand[CAND_CAP];
__device__ int      g_cand_cnt;          // zero-init; re-zeroed by k_select_nms
__device__ int      g_hist[NBUCK];       // zero-init; re-zeroed by k_select_nms
__device__ unsigned char g_cls[N_ANCHS];
__device__ float4   g_fbox[K_DETS];
__device__ int      g_keep[K_DETS];

__constant__ float c_mean[3] = {0.485f, 0.456f, 0.406f};
__constant__ float c_istd[3] = {1.0f/0.229f, 1.0f/0.224f, 1.0f/0.225f};

// ---------------------------------------------------------------------------
// k_score: thread = (anchor-quad, channel-group-of-20), FULL unroll for MLP,
// shfl butterflies to combine groups.
__global__ void k_score(const float* __restrict__ raw) {
    int gid = blockIdx.x * blockDim.x + threadIdx.x;
    int q = gid >> 2;          // anchor quad 0..25199
    int g = gid & 3;           // channel group 0..3
    bool active = (q < N_ANCHS / 4);
    if (!active) q = 0;

    const float4* lg = (const float4*)(raw + 5 * N_ANCHS);
    const int QN = N_ANCHS / 4;

    float best[4] = {-3.4e38f, -3.4e38f, -3.4e38f, -3.4e38f};
    int   bc[4]   = {0, 0, 0, 0};
    int c0 = g * 20;
    #pragma unroll
    for (int c = 0; c < 20; c++) {
        float4 v = lg[(c0 + c) * QN + q];
        if (v.x > best[0]) { best[0] = v.x; bc[0] = c0 + c; }
        if (v.y > best[1]) { best[1] = v.y; bc[1] = c0 + c; }
        if (v.z > best[2]) { best[2] = v.z; bc[2] = c0 + c; }
        if (v.w > best[3]) { best[3] = v.w; bc[3] = c0 + c; }
    }
    #pragma unroll
    for (int off = 1; off <= 2; off <<= 1) {
        #pragma unroll
        for (int k = 0; k < 4; k++) {
            float ob = __shfl_xor_sync(0xffffffffu, best[k], off);
            int   oc = __shfl_xor_sync(0xffffffffu, bc[k],  off);
            if (ob > best[k] || (ob == best[k] && oc < bc[k])) {
                best[k] = ob; bc[k] = oc;
            }
        }
    }
    if (!active || g != 0) return;

    int i0 = q * 4;
    uchar4 cw = make_uchar4((unsigned char)bc[0], (unsigned char)bc[1],
                            (unsigned char)bc[2], (unsigned char)bc[3]);
    *(uchar4*)(g_cls + i0) = cw;

    #pragma unroll
    for (int k = 0; k < 4; k++) {
        int i = i0 + k;
        int cls = bc[k] + 1;
        bool allowed = (cls==1)|(cls==2)|(cls==3)|(cls==4)|(cls==6)|(cls==8)|
                       (cls==17)|(cls==18)|(cls==44);
        if (allowed && best[k] > 0.1f) {
            int b = (int)(best[k] * 170.0f);
            b = max(0, min(NBUCK - 1, b));
            atomicAdd(&g_hist[b], 1);
            int pos = atomicAdd(&g_cand_cnt, 1);
            if (pos < CAND_CAP) {
                unsigned long long key =
                    ((unsigned long long)__float_as_uint(best[k]) << 32) |
                    (unsigned long long)(0xFFFFFFFFu - (unsigned)i);
                g_cand[pos] = key;
            }
        }
    }
}

// ---------------------------------------------------------------------------
// Fused top-K selection + NMS + scalar outputs. One block, 1024 threads.
__global__ void k_select_nms(const float* __restrict__ raw, float* __restrict__ out) {
    __shared__ int sh[NBUCK];
    __shared__ int s_wsum[32], s_wexcl[32];
    __shared__ unsigned long long keys[SORT_N];
    __shared__ unsigned long long s_sorted[K_DETS];
    __shared__ float sx1[K_DETS], sy1[K_DETS], sx2[K_DETS], sy2[K_DETS], sar[K_DETS];
    __shared__ float sscore[K_DETS];
    __shared__ int   sidx[K_DETS];
    __shared__ unsigned char svalid[K_DETS];
    __shared__ unsigned s_mask[K_DETS * NMS_WORDS];
    __shared__ unsigned char s_kp[K_DETS];
    __shared__ int s_B, s_sel;
    int t = threadIdx.x;
    int lane = t & 31, wrp = t >> 5;

    // --- Phase A: suffix-sum of histogram via shfl (2 barriers) ---
    {
        int sfx = g_hist[t];
        #pragma unroll
        for (int off = 1; off < 32; off <<= 1) {
            int nv = __shfl_down_sync(0xffffffffu, sfx, off);
            if (lane + off < 32) sfx += nv;
        }
        if (lane == 0) s_wsum[wrp] = sfx;
        if (t == 0) { s_sel = 0; s_B = 0; }
        __syncthreads();
        if (t < 32) {
            int wv = s_wsum[t];
            int ws = wv;
            #pragma unroll
            for (int off = 1; off < 32; off <<= 1) {
                int nv = __shfl_down_sync(0xffffffffu, ws, off);
                if (t + off < 32) ws += nv;
            }
            s_wexcl[t] = ws - wv;     // sum over warps > t
        }
        __syncthreads();
        sh[t] = sfx + s_wexcl[wrp];   // suffix sum from bucket t
    }
    __syncthreads();

    int n_stored = min(g_cand_cnt, CAND_CAP);
    int total = sh[0];
    int target = min(K_DETS, min(total, n_stored));
    if (target > 0) {
        if (sh[t] >= target && (t == NBUCK - 1 || sh[t + 1] < target)) s_B = t;
    }
    keys[t] = 0ull;
    __syncthreads();
    int B = s_B;

    // --- Phase B: gather survivors ---
    if (target > 0) {
        for (int i = t; i < n_stored; i += blockDim.x) {
            unsigned long long key = g_cand[i];
            float s = __uint_as_float((unsigned)(key >> 32));
            int b = (int)(s * 170.0f);
            b = max(0, min(NBUCK - 1, b));
            if (b >= B) {
                int p = atomicAdd(&s_sel, 1);
                if (p < SORT_N) keys[p] = key;
            }
        }
    }
    __syncthreads();

    // --- Phase C: rank-based selection (keys unique -> ranks distinct) ---
    {
        int n = min(s_sel, SORT_N);
        if (t < n) {
            unsigned long long mykey = keys[t];
            int rank = 0;
            for (int i = 0; i < n; i++)
                rank += (keys[i] > mykey) ? 1 : 0;
            if (rank < K_DETS) s_sorted[rank] = mykey;
        }
    }
    __syncthreads();

    // --- Phase D: decode top-300 boxes into smem; re-zero persistent state ---
    if (t < K_DETS) {
        int idx = -1;
        float sc = 0.0f;
        if (t < target) {
            unsigned long long key = s_sorted[t];
            idx = (int)(0xFFFFFFFFu - (unsigned)(key & 0xFFFFFFFFull));
            sc  = __uint_as_float((unsigned)(key >> 32));
        }
        sidx[t]   = idx;
        sscore[t] = sc;
        float x1 = 0.f, y1 = 0.f, x2 = 0.f, y2 = 0.f;
        if (idx >= 0) {
            float cx = raw[idx];
            float cy = raw[N_ANCHS + idx];
            float w  = raw[2 * N_ANCHS + idx];
            float h  = raw[3 * N_ANCHS + idx];
            x1 = cx - w * 0.5f; y1 = cy - h * 0.5f;
            x2 = cx + w * 0.5f; y2 = cy + h * 0.5f;
        }
        sx1[t] = x1; sy1[t] = y1; sx2[t] = x2; sy2[t] = y2;
        sar[t] = (x2 - x1) * (y2 - y1);
        svalid[t] = (idx >= 0) ? 1 : 0;
    }
    g_hist[t] = 0;
    if (t == 0) g_cand_cnt = 0;
    __syncthreads();

    // --- Phase E: mask build (div-free IOU: inter/uni>thr <=> inter>thr*uni,
    // uni>0; degenerate zero-area rows give inter=uni=0 -> false as in ref) ---
    {
        for (int i = wrp; i < K_DETS; i += 32) {
            float ix1 = sx1[i], iy1 = sy1[i], ix2 = sx2[i], iy2 = sy2[i], ia = sar[i];
            #pragma unroll
            for (int w = 0; w < NMS_WORDS; w++) {
                int j = (w << 5) + lane;
                bool sup = false;
                if (j < K_DETS && j > i) {
                    float lx = fmaxf(ix1, sx1[j]);
                    float ly = fmaxf(iy1, sy1[j]);
                    float rx = fminf(ix2, sx2[j]);
                    float ry = fminf(iy2, sy2[j]);
                    float iw = fmaxf(rx - lx, 0.0f);
                    float ih = fmaxf(ry - ly, 0.0f);
                    float inter = iw * ih;
                    float uni = ia + sar[j] - inter;
                    sup = inter > 0.45f * uni;
                }
                unsigned m = __ballot_sync(0xffffffffu, sup);
                if (lane == 0) s_mask[i * NMS_WORDS + w] = m;
            }
        }
    }
    __syncthreads();

    // --- Phase F: greedy scan, warp 0; lane w owns removal word w ---
    if (t < 32) {
        unsigned rm = 0;
        #pragma unroll
        for (int w = 0; w < NMS_WORDS; w++) {
            int j = (w << 5) + t;
            bool inv = (j < K_DETS) ? (svalid[j] == 0) : false;
            unsigned bword = __ballot_sync(0xffffffffu, inv);
            if (t == w) rm = bword;
        }
        unsigned cur = (t < NMS_WORDS) ? s_mask[t] : 0;
        for (int i = 0; i < K_DETS; i++) {
            unsigned nxt = (t < NMS_WORDS && i + 1 < K_DETS)
                           ? s_mask[(i + 1) * NMS_WORDS + t] : 0;
            unsigned word = __shfl_sync(0xffffffffu, rm, i >> 5);
            bool alive = !((word >> (i & 31)) & 1u);
            if (alive) rm |= cur;
            if (t == 0) s_kp[i] = alive ? 1 : 0;
            cur = nxt;
        }
    }
    __syncthreads();

    // --- Phase G: scalar outputs ---
    if (t < K_DETS) {
        int k = s_kp[t];
        float fx1 = k ? sx1[t] : 0.f, fy1 = k ? sy1[t] : 0.f;
        float fx2 = k ? sx2[t] : 0.f, fy2 = k ? sy2[t] : 0.f;
        out[OFF_BOXES + 4 * t + 0] = fx1;
        out[OFF_BOXES + 4 * t + 1] = fy1;
        out[OFF_BOXES + 4 * t + 2] = fx2;
        out[OFF_BOXES + 4 * t + 3] = fy2;
        out[OFF_SCORES + t] = k ? sscore[t] : 0.0f;
        int cv = 0;
        int idx = sidx[t];
        if (k && idx >= 0) cv = (int)g_cls[idx] + 1;
        out[OFF_CLASSES + t] = (float)cv;
        out[OFF_KEEP + t]    = k ? 1.0f : 0.0f;
        g_fbox[t] = make_float4(fx1, fy1, fx2, fy2);
        g_keep[t] = k;
    }
}

// ---------------------------------------------------------------------------
// Crops: grid (24, 301). b==0 -> full-image resize. b>0 -> ROI with
// float4-staged smem window, bitcast y-table, register row cache, full unroll.
__global__ void __launch_bounds__(224) k_crops(const float* __restrict__ img,
                                               float* __restrict__ out) {
    __shared__ float s_img[S_NY * S_NXS];
    __shared__ float4 s_yt[ROWS_PER_SLAB];
    int t = threadIdx.x;                // xo 0..223
    int b = blockIdx.y;                 // 0..300
    int c = blockIdx.x >> 3;            // 0..2
    int slab = blockIdx.x & 7;          // 0..7
    int r0 = slab * ROWS_PER_SLAB;

    float istd = c_istd[c];
    float nmean = -c_mean[c] * istd;
    float* dst = out + OFF_CROPS + (size_t)b * CROP_ELEMS + c * CH_ELEMS
                 + r0 * OUTSZ + t;
    const float* base = img + c * IMG2;
    const float inv = 1.0f / (float)OUTSZ;

    if (b == 0) {
        float xs = ((float)t + 0.5f) * inv * (float)IMG_W - 0.5f;
        float xc = fminf(fmaxf(xs, 0.0f), (float)(IMG_W - 1));
        int x0 = (int)floorf(xc);
        int x1i = min(x0 + 1, IMG_W - 1);
        float lx = xc - (float)x0;
        #pragma unroll 4
        for (int row = 0; row < ROWS_PER_SLAB; row++) {
            float ys = ((float)(r0 + row) + 0.5f) * inv * (float)IMG_W - 0.5f;
            float yc = fminf(fmaxf(ys, 0.0f), (float)(IMG_W - 1));
            int y0 = (int)floorf(yc);
            int y1 = min(y0 + 1, IMG_W - 1);
            float ly = yc - (float)y0;
            const float* p0 = base + y0 * IMG_W;
            const float* p1 = base + y1 * IMG_W;
            float v00 = p0[x0], v01 = p0[x1i], v10 = p1[x0], v11 = p1[x1i];
            float top = fmaf(v01 - v00, lx, v00);
            float bot = fmaf(v11 - v10, lx, v10);
            float val = fmaf(bot - top, ly, top);
            dst[row * OUTSZ] = fmaf(val, istd, nmean);
        }
        return;
    }

    int kpF = g_keep[b - 1];
    if (!kpF) {
        float z = nmean;
        float4 z4 = make_float4(z, z, z, z);
        float4* d4 = (float4*)(out + OFF_CROPS + (size_t)b * CROP_ELEMS
                               + c * CH_ELEMS + r0 * OUTSZ);
        #pragma unroll
        for (int i = 0; i < SLAB_PX / 4 / 224; i++)
            d4[i * 224 + t] = z4;
        return;
    }
    float4 bb = g_fbox[b - 1];
    float w = bb.z - bb.x, h = bb.w - bb.y;

    // Source-window bounds (uniform per block).
    float xsA = bb.x - 0.5f + (0.5f   * inv) * w;
    float xsB = bb.x - 0.5f + (223.5f * inv) * w;
    int X0 = (int)floorf(fminf(fmaxf(xsA, 0.0f), (float)(IMG_W - 1)));
    int Xe = (int)floorf(fminf(fmaxf(xsB, 0.0f), (float)(IMG_W - 1)));
    int X0a = X0 & ~3;                          // 16B-aligned start
    int XHI = min(Xe + 1, IMG_W - 1);
    int NXa = XHI - X0a + 1;                    // valid staged width
    int NXs = (NXa + 3) & ~3;                   // padded smem stride
    NXs = min(NXs, S_NXS);
    float ysA = bb.y - 0.5f + (((float)r0 + 0.5f)  * inv) * h;
    float ysB = bb.y - 0.5f + (((float)r0 + 27.5f) * inv) * h;
    int Y0 = (int)floorf(fminf(fmaxf(ysA, 0.0f), (float)(IMG_W - 1)));
    int Ye = (int)floorf(fminf(fmaxf(ysB, 0.0f), (float)(IMG_W - 1)));
    int NY = min(Ye + 1, IMG_W - 1) - Y0 + 1;
    NY = min(NY, S_NY);

    // y-table: (ly, bitcast(yr*NXs), bitcast(yr1*NXs), vy).
    if (t < ROWS_PER_SLAB) {
        float ys = bb.y - 0.5f + (((float)(r0 + t) + 0.5f) * inv) * h;
        float vy = (ys >= -1.0f && ys <= (float)IMG_W) ? 1.0f : 0.0f;
        float yc = fminf(fmaxf(ys, 0.0f), (float)(IMG_W - 1));
        float y0f = floorf(yc);
        int yr = (int)y0f - Y0;
        int yr1 = min(yr + 1, NY - 1);
        s_yt[t] = make_float4(yc - y0f, __int_as_float(yr * NXs),
                              __int_as_float(yr1 * NXs), vy);
    }

    // float4 staging: rows are 16B-aligned from base+Y0*IMG_W+X0a.
    {
        int n4 = NXs >> 2;
        int tot4 = NY * n4;
        unsigned magic = 0xFFFFFFFFu / (unsigned)n4 + 1u;
        const float4* src4 = (const float4*)(base + Y0 * IMG_W + X0a);
        int limit4 = (IMG2 - (Y0 * IMG_W + X0a)) / 4 - 1;  // stay inside image
        float4* s4 = (float4*)s_img;
        for (int i = t; i < tot4; i += 224) {
            int row = (int)__umulhi((unsigned)i, magic);
            int col = i - row * n4;
            int off = min(row * IMG_W4 + col, limit4);     // clamped lanes land
            s4[row * n4 + col] = src4[off];                // only in padding
        }
    }
    __syncthreads();

    float xs = bb.x - 0.5f + (((float)t + 0.5f) * inv) * w;
    float vx = (xs >= -1.0f && xs <= (float)IMG_W) ? 1.0f : 0.0f;
    float xc = fminf(fmaxf(xs, 0.0f), (float)(IMG_W - 1));
    float x0f = floorf(xc);
    float lx = xc - x0f;
    int xr = (int)x0f - X0a;
    int xr1 = min(xr + 1, NXa - 1);
    float a = vx * istd;                 // folded validity*scale (per thread)

    float t00 = 0.f, t01 = 0.f, b00 = 0.f, b01 = 0.f;
    int prevYo = -1000, prevYo1 = -1000;

    #pragma unroll
    for (int row = 0; row < ROWS_PER_SLAB; row++) {
        float4 yt = s_yt[row];           // broadcast LDS.128
        int yo  = __float_as_int(yt.y);  // yr*NXs (bitcast, no F2I)
        int yo1 = __float_as_int(yt.z);  // yr1*NXs
        float ly = yt.x;

        if (yo != prevYo) {              // warp-uniform
            if (yo == prevYo1) { t00 = b00; t01 = b01; }
            else {
                t00 = s_img[yo + xr];
                t01 = s_img[yo + xr1];
            }
        }
        if (yo1 != prevYo1) {            // warp-uniform
            if (yo1 == yo) { b00 = t00; b01 = t01; }
            else {
                b00 = s_img[yo1 + xr];
                b01 = s_img[yo1 + xr1];
            }
        }
        prevYo = yo; prevYo1 = yo1;

        float top = fmaf(t01 - t00, lx, t00);
        float bot = fmaf(b01 - b00, lx, b00);
        float val = fmaf(bot - top, ly, top);
        float s   = a * yt.w;            // vx*vy*istd
        dst[row * OUTSZ] = fmaf(val, s, nmean);
    }
}

// ---------------------------------------------------------------------------
extern "C" void kernel_launch(void* const* d_in, const int* in_sizes, int n_in,
                              void* d_out, int out_size) {
    const float* raw = (const float*)d_in[0];   // (1,85,100800)
    const float* img = (const float*)d_in[1];   // (1,3,1280,1280)
    float* out = (float*)d_out;

    k_score<<<(N_ANCHS + 255) / 256, 256>>>(raw);
    k_select_nms<<<1, 1024>>>(raw, out);
    dim3 g(24, 301);                            // (3 ch x 8 slabs, 301 crops)
    k_crops<<<g, 224>>>(img, out);
}